// round 13
// baseline (speedup 1.0000x reference)
#include <cuda_runtime.h>
#include <cstdint>

#define LL   50
#define DD   64
#define EE   128
#define UU   256     // hidden units total
#define UH   128     // hidden units per pass (2 passes)
#define NT   256     // 8 warps; 2 CTAs/SM

#define FFMA2(acc, w, k) asm("fma.rn.f32x2 %0, %1, %2, %0;" : "+l"(acc) : "l"(w), "l"(k))
#define PACK2(dst, f)    asm("mov.b64 %0, {%1, %1};" : "=l"(dst) : "r"(__float_as_uint(f)))
#define UNPK2(lo, hi, s) do { unsigned _ulo, _uhi; \
    asm("mov.b64 {%0, %1}, %2;" : "=r"(_ulo), "=r"(_uhi) : "l"(s)); \
    lo = __uint_as_float(_ulo); hi = __uint_as_float(_uhi); } while (0)

// smem floats: sW2q 128*128 | sk 6400 | sq 128 | sAbh 128 | sAq 8*128 | sWout 256 | s_part[4][64]
#define SMEM_FLOATS (128*UH + 6400 + 128 + 128 + 1024 + 256 + 256)
#define SMEM_BYTES  (SMEM_FLOATS*4 + 64*4)

extern "C" __global__ void __launch_bounds__(NT, 2)
din_fused_kernel(const int*   __restrict__ qid_item,
                 const int*   __restrict__ qid_cate,
                 const int*   __restrict__ sid_item,
                 const int*   __restrict__ sid_cate,
                 const int*   __restrict__ mask,    // bool widened to 4B; nonzero == true
                 const float* __restrict__ emb_item,
                 const float* __restrict__ emb_cate,
                 const float* __restrict__ W_hide,
                 const float* __restrict__ b_hide,
                 const float* __restrict__ W_out,
                 const float* __restrict__ b_out,
                 float*       __restrict__ out)
{
    extern __shared__ float smem[];
    float* sW2q   = smem;                    // [128 d][128 u_local] (reused per pass)
    float* sk     = sW2q + 128*UH;           // [50][128]
    float* sq     = sk   + LL*EE;            // [128]
    float* sAbh   = sq   + 128;              // [128] (per pass)
    float* sAq    = sAbh + 128;              // [8][128] strip partials
    float* sWout  = sAq  + 8*UH;             // [256]
    float* s_part = sWout + UU;              // [4][64]: (pass,ucol) partial scores
    int*   sactive= (int*)(s_part + 256);    // [56]
    int*   scnt   = sactive + 56;            // [2]

    const int b    = blockIdx.x;
    const int tid  = threadIdx.x;
    const int warp = tid >> 5;
    const int lane = tid & 31;

    // ---------------- Phase 1: gathers + ballot compaction ------------------
    unsigned bal = 0; bool act = false;
    if (warp < 2) {
        const int l = (warp << 5) + lane;
        act = (l < LL) && (mask[(size_t)b*LL + l] != 0);
        bal = __ballot_sync(0xffffffffu, act);
        if (lane == 0) scnt[warp] = __popc(bal);
    }
    if (tid < EE) {
        const int qi = qid_item[b];
        const int qc = qid_cate[b];
        sq[tid] = (tid < DD) ? emb_item[(size_t)qi*DD + tid]
                             : emb_cate[(size_t)qc*DD + (tid - DD)];
    }
    sWout[tid] = W_out[tid];                  // NT == 256 == UU
    // K gather, float4: 50*32 float4 cells
    for (int idx = tid; idx < LL*32; idx += NT) {
        const int l  = idx >> 5;
        const int e4 = idx & 31;
        float4 v;
        if (e4 < 16) v = *(const float4*)(emb_item + (size_t)sid_item[(size_t)b*LL + l]*DD + (e4 << 2));
        else         v = *(const float4*)(emb_cate + (size_t)sid_cate[(size_t)b*LL + l]*DD + ((e4 - 16) << 2));
        *(float4*)(sk + (l << 7) + (e4 << 2)) = v;
    }
    __syncthreads();

    // compaction write (deterministic order via ballot prefix)
    if (warp < 2 && act) {
        const int off = (warp == 1) ? scnt[0] : 0;
        sactive[off + __popc(bal & ((1u << lane) - 1u))] = (warp << 5) + lane;
    }
    __syncthreads();

    const int nact = scnt[0] + scnt[1];

    // ================= Two passes over u-halves ==============================
    #pragma unroll 1
    for (int h = 0; h < 2; h++) {
        const int gub = h << 7;               // global u base of this half

        // ---- Phase 2: fold W2q = Wk + q*Wp for this half; Aq partials -------
        {
            const int u4 = lane << 2;         // 4 consecutive local u
            const int d0 = warp << 4;         // 16 d-rows per warp strip
            const int gu = gub + u4;
            float4 aq = make_float4(0.f, 0.f, 0.f, 0.f);
            #pragma unroll 4
            for (int i = 0; i < 16; i++) {
                const int d = d0 + i;
                const float qd = sq[d];
                const float4 wk = *(const float4*)(W_hide + (size_t)(128 + d)*UU + gu);
                const float4 wp = *(const float4*)(W_hide + (size_t)(256 + d)*UU + gu);
                const float4 wq = *(const float4*)(W_hide + (size_t)d*UU + gu);
                float4 w2;
                w2.x = fmaf(qd, wp.x, wk.x);
                w2.y = fmaf(qd, wp.y, wk.y);
                w2.z = fmaf(qd, wp.z, wk.z);
                w2.w = fmaf(qd, wp.w, wk.w);
                *(float4*)(sW2q + (d << 7) + u4) = w2;
                aq.x = fmaf(qd, wq.x, aq.x);
                aq.y = fmaf(qd, wq.y, aq.y);
                aq.z = fmaf(qd, wq.z, aq.z);
                aq.w = fmaf(qd, wq.w, aq.w);
            }
            *(float4*)(sAq + warp*UH + u4) = aq;
        }
        __syncthreads();
        if (tid < UH) {
            float a = b_hide[gub + tid];
            #pragma unroll
            for (int s = 0; s < 8; s++) a += sAq[s*UH + tid];
            sAbh[tid] = a;
        }
        __syncthreads();

        // ---- Phase 3: 2-D warp tiling: uc (2 u-cols) x wl (4 l-tiles) --------
        // warp = wl*2 + uc; sweep covers l = base + wl + 4t; base loop covers nact>32
        {
            const int uc = warp & 1;
            const int wl = warp >> 1;
            const int ub = (uc << 6) + (lane << 1);   // local u pair base

            for (int base = 0; base < nact; base += 32) {
                int koff[8];
                #pragma unroll
                for (int t = 0; t < 8; t++) {
                    const int li = base + wl + (t << 2);
                    koff[t] = sactive[(li < nact) ? li : 0] << 7;
                }

                const unsigned long long iA = *(const unsigned long long*)(sAbh + ub);
                unsigned long long A[8];
                #pragma unroll
                for (int t = 0; t < 8; t++) A[t] = iA;

                for (int d0 = 0; d0 < EE; d0 += 4) {
                    unsigned long long wA[4];
                    #pragma unroll
                    for (int dd = 0; dd < 4; dd++)
                        wA[dd] = *(const unsigned long long*)(sW2q + ((d0 + dd) << 7) + ub);

                    float4 kv[8];
                    #pragma unroll
                    for (int t = 0; t < 8; t++)
                        kv[t] = *(const float4*)(sk + koff[t] + d0);   // broadcast LDS.128

                    #pragma unroll
                    for (int dd = 0; dd < 4; dd++) {
                        #pragma unroll
                        for (int t = 0; t < 8; t++) {
                            unsigned long long kp;
                            PACK2(kp, ((const float*)&kv[t])[dd]);
                            FFMA2(A[t], wA[dd], kp);
                        }
                    }
                }

                // relu + W_out dot (partial over this warp's 2 u's per lane)
                const float w0 = sWout[gub + ub], w1 = sWout[gub + ub + 1];
                float s[8];
                #pragma unroll
                for (int t = 0; t < 8; t++) {
                    float lo, hi;
                    UNPK2(lo, hi, A[t]);
                    s[t] = fmaxf(lo, 0.f)*w0 + fmaxf(hi, 0.f)*w1;
                }
                #pragma unroll
                for (int t = 0; t < 8; t++) {
                    #pragma unroll
                    for (int off = 16; off > 0; off >>= 1)
                        s[t] += __shfl_xor_sync(0xffffffffu, s[t], off);
                }
                if (lane == 0) {
                    float* dst = s_part + ((h << 1) + uc) * 64;
                    #pragma unroll
                    for (int t = 0; t < 8; t++) {
                        const int li = base + wl + (t << 2);
                        if (li < nact) dst[li] = s[t];
                    }
                }
            }
        }
        __syncthreads();   // sW2q/sAbh reused next pass; s_part rows complete
    }

    // ---------------- Phase 4: combine parts + weighted sum + store ----------
    if (tid < EE) {
        const float bo = b_out[0];
        float acc = 0.f;
        for (int i = 0; i < nact; i++) {
            const float sc = ((s_part[i] + s_part[64 + i]) + (s_part[128 + i] + s_part[192 + i])) + bo;
            acc = fmaf(sc, sk[(sactive[i] << 7) + tid], acc);
        }
        out[(size_t)b*EE + tid] = acc;
    }
}

extern "C" void kernel_launch(void* const* d_in, const int* in_sizes, int n_in,
                              void* d_out, int out_size)
{
    const int*   qid_item = (const int*)  d_in[0];
    const int*   qid_cate = (const int*)  d_in[1];
    const int*   sid_item = (const int*)  d_in[2];
    const int*   sid_cate = (const int*)  d_in[3];
    const int*   mask     = (const int*)  d_in[4];
    const float* emb_item = (const float*)d_in[5];
    const float* emb_cate = (const float*)d_in[6];
    const float* W_hide   = (const float*)d_in[7];
    const float* b_hide   = (const float*)d_in[8];
    const float* W_out    = (const float*)d_in[9];
    const float* b_out    = (const float*)d_in[10];
    float*       out      = (float*)      d_out;

    const int B = in_sizes[0];

    cudaFuncSetAttribute(din_fused_kernel,
                         cudaFuncAttributeMaxDynamicSharedMemorySize, SMEM_BYTES);

    din_fused_kernel<<<B, NT, SMEM_BYTES>>>(
        qid_item, qid_cate, sid_item, sid_cate, mask,
        emb_item, emb_cate, W_hide, b_hide, W_out, b_out, out);
}